// round 6
// baseline (speedup 1.0000x reference)
#include <cuda_runtime.h>
#include <math.h>

// Problem constants
#define NN 20000
#define EE 200000
#define BBATCH 16
#define ND 64
#define ED 32
#define GD 32
#define HD 128
#define DOF 6
#define PI_F 3.14159265358979f

// ---------------------------------------------------------------------------
// Scratch (static __device__ arrays; no allocation allowed)
// ---------------------------------------------------------------------------
__device__ float g_AB[(size_t)NN * 256];     // per-node A (x@W1a) [0:128], B (x@W1b) [128:256]
__device__ float g_accum[(size_t)NN * HD];   // segment sums
__device__ float g_cnt[NN];                  // segment counts

__device__ __forceinline__ void fma4(float4& a, float s, const float4& w) {
    a.x = fmaf(s, w.x, a.x);
    a.y = fmaf(s, w.y, a.y);
    a.z = fmaf(s, w.z, a.z);
    a.w = fmaf(s, w.w, a.w);
}

__device__ __forceinline__ float4 relu4(float4 v) {
    v.x = fmaxf(v.x, 0.f); v.y = fmaxf(v.y, 0.f);
    v.z = fmaxf(v.z, 0.f); v.w = fmaxf(v.w, 0.f);
    return v;
}

__device__ __forceinline__ void red_add_v4(float* p, float4 v) {
    asm volatile("red.global.add.v4.f32 [%0], {%1,%2,%3,%4};"
                 :: "l"(p), "f"(v.x), "f"(v.y), "f"(v.z), "f"(v.w) : "memory");
}

// ---------------------------------------------------------------------------
// Kernel 1: per-node precompute A = x@W1[0:64], B = x@W1[64:128]; zero accum/cnt
// block = 256 threads, tile = 32 nodes, persistent grid-stride
// smem: W1ab 128x128 (65536B) + X 32x68 (8704B) = 74240B
// ---------------------------------------------------------------------------
#define PRE_SMEM ((128 * 128 + 32 * 68) * 4)

__global__ void __launch_bounds__(256, 1)
k_pre(const float* __restrict__ xfeat, const float* __restrict__ W1) {
    extern __shared__ float sm[];
    float* sW = sm;              // 128*128
    float* sX = sm + 128 * 128;  // 32*68 (padded)

    for (int idx = threadIdx.x; idx < (128 * 128) / 4; idx += 256)
        ((float4*)sW)[idx] = ((const float4*)W1)[idx];

    const int warp = threadIdx.x >> 5, lane = threadIdx.x & 31;

    for (int tile = blockIdx.x; tile < NN / 32; tile += gridDim.x) {
        const int nb = tile * 32;
        __syncthreads();
        for (int idx = threadIdx.x; idx < 32 * 16; idx += 256) {
            int n = idx >> 4, k4 = idx & 15;
            ((float4*)(sX + n * 68))[k4] =
                ((const float4*)(xfeat + (size_t)(nb + n) * 64))[k4];
        }
        __syncthreads();

        float4 accA[4], accB[4];
#pragma unroll
        for (int r = 0; r < 4; r++) {
            accA[r] = make_float4(0.f, 0.f, 0.f, 0.f);
            accB[r] = make_float4(0.f, 0.f, 0.f, 0.f);
        }
#pragma unroll 4
        for (int k = 0; k < 64; k++) {
            float4 wa = ((float4*)(sW + k * 128))[lane];
            float4 wb = ((float4*)(sW + (64 + k) * 128))[lane];
#pragma unroll
            for (int r = 0; r < 4; r++) {
                float x = sX[(4 * warp + r) * 68 + k];
                fma4(accA[r], x, wa);
                fma4(accB[r], x, wb);
            }
        }
#pragma unroll
        for (int r = 0; r < 4; r++) {
            int gn = nb + 4 * warp + r;
            ((float4*)(g_AB + (size_t)gn * 256))[lane] = accA[r];
            ((float4*)(g_AB + (size_t)gn * 256 + 128))[lane] = accB[r];
            ((float4*)(g_accum + (size_t)gn * 128))[lane] = make_float4(0.f, 0.f, 0.f, 0.f);
            if (lane == 0) g_cnt[gn] = 0.f;
        }
    }
}

// ---------------------------------------------------------------------------
// Kernel 2: fused edge MLP (layer1 factorized + layer2 GEMM) + atomic scatter
// block = 512 threads (16 warps), tile = 64 edges -> 128 direction-rows
// ---------------------------------------------------------------------------
// smem float offsets
#define EO_W2  0       // 128*128 = 16384
#define EO_W1E 16384   // 32*128  = 4096
#define EO_W1P 20480   // 12*128  = 1536
#define EO_B1  22016   // 128
#define EO_B2  22144   // 128
#define EO_EF  22272   // 64*32   = 2048
#define EO_P   24320   // 128*12  = 1536
#define EO_H1  25856   // 128*132 = 16896
#define EO_TGT 42752   // 128 ints
#define EDGE_SMEM ((42752 + 128) * 4)   // 171,520 B

__global__ void __launch_bounds__(512, 1)
k_edge(const float* __restrict__ T_R, const float* __restrict__ T_t,
       const float* __restrict__ edge_feat,
       const float* __restrict__ Tij_R, const float* __restrict__ Tij_t,
       const int* __restrict__ edge_index,
       const float* __restrict__ W1, const float* __restrict__ b1,
       const float* __restrict__ W2, const float* __restrict__ b2) {
    extern __shared__ float sm[];
    float* sW2  = sm + EO_W2;
    float* sW1e = sm + EO_W1E;
    float* sW1p = sm + EO_W1P;
    float* sb1  = sm + EO_B1;
    float* sb2  = sm + EO_B2;
    float* sEF  = sm + EO_EF;
    float* sP   = sm + EO_P;
    float* sH1  = sm + EO_H1;
    int*   sTgt = (int*)(sm + EO_TGT);

    const int tid = threadIdx.x;
    for (int idx = tid; idx < 16384 / 4; idx += 512)
        ((float4*)sW2)[idx] = ((const float4*)W2)[idx];
    for (int idx = tid; idx < 4096 / 4; idx += 512)
        ((float4*)sW1e)[idx] = ((const float4*)(W1 + 128 * 128))[idx];
    for (int idx = tid; idx < 1536 / 4; idx += 512)
        ((float4*)sW1p)[idx] = ((const float4*)(W1 + 160 * 128))[idx];
    if (tid < 128) { sb1[tid] = b1[tid]; sb2[tid] = b2[tid]; }

    const int warp = tid >> 5, lane = tid & 31;

    for (int tile = blockIdx.x; tile < EE / 64; tile += gridDim.x) {
        const int eb = tile * 64;
        __syncthreads();   // previous tile fully consumed

        // edge_feat tile (contiguous, coalesced)
        {
            int idx = tid;   // exactly 512 float4s
            ((float4*)sEF)[idx] = ((const float4*)(edge_feat + (size_t)eb * 32))[idx];
        }

        // pose vectors: one thread per edge
        if (tid < 64) {
            const int e = tid, ge = eb + e;
            const int gi = edge_index[ge];
            const int gj = edge_index[EE + ge];
            sTgt[2 * e]     = gj;   // f_ij aggregates into j
            sTgt[2 * e + 1] = gi;   // f_ji aggregates into i

            float Ri[9], Rj[9], TRm[9], ti[3], tj[3], Tt[3];
#pragma unroll
            for (int k = 0; k < 9; k++) {
                Ri[k]  = T_R[(size_t)gi * 9 + k];
                Rj[k]  = T_R[(size_t)gj * 9 + k];
                TRm[k] = Tij_R[(size_t)ge * 9 + k];
            }
#pragma unroll
            for (int k = 0; k < 3; k++) {
                ti[k] = T_t[(size_t)gi * 3 + k];
                tj[k] = T_t[(size_t)gj * 3 + k];
                Tt[k] = Tij_t[(size_t)ge * 3 + k];
            }
            // Ra = Rj * Ri^T ; ta = tj - Ra*ti
            float Ra[9], ta[3];
#pragma unroll
            for (int r = 0; r < 3; r++) {
#pragma unroll
                for (int c = 0; c < 3; c++)
                    Ra[r * 3 + c] = Rj[r * 3 + 0] * Ri[c * 3 + 0]
                                  + Rj[r * 3 + 1] * Ri[c * 3 + 1]
                                  + Rj[r * 3 + 2] * Ri[c * 3 + 2];
                ta[r] = tj[r] - (Ra[r * 3 + 0] * ti[0] + Ra[r * 3 + 1] * ti[1]
                               + Ra[r * 3 + 2] * ti[2]);
            }
            // e_ij = (Ra, ta) * inv(Tij): R = Ra*TR^T, t = ta - R*Tt
            {
                float* pv = sP + (2 * e) * 12;
#pragma unroll
                for (int r = 0; r < 3; r++) {
                    float re[3];
#pragma unroll
                    for (int c = 0; c < 3; c++)
                        re[c] = Ra[r * 3 + 0] * TRm[c * 3 + 0]
                              + Ra[r * 3 + 1] * TRm[c * 3 + 1]
                              + Ra[r * 3 + 2] * TRm[c * 3 + 2];
                    float te = ta[r] - (re[0] * Tt[0] + re[1] * Tt[1] + re[2] * Tt[2]);
                    pv[4 * r + 0] = re[0]; pv[4 * r + 1] = re[1];
                    pv[4 * r + 2] = re[2]; pv[4 * r + 3] = te;
                }
            }
            // e_ji: Rb = Ra^T, tb = ti - Rb*tj; R = Rb*TR, t = Rb*Tt + tb
            {
                float* pv = sP + (2 * e + 1) * 12;
#pragma unroll
                for (int r = 0; r < 3; r++) {
                    float b0 = Ra[0 * 3 + r], b1v = Ra[1 * 3 + r], b2v = Ra[2 * 3 + r];
                    float tb = ti[r] - (b0 * tj[0] + b1v * tj[1] + b2v * tj[2]);
                    float re[3];
#pragma unroll
                    for (int c = 0; c < 3; c++)
                        re[c] = b0 * TRm[0 * 3 + c] + b1v * TRm[1 * 3 + c] + b2v * TRm[2 * 3 + c];
                    float te = b0 * Tt[0] + b1v * Tt[1] + b2v * Tt[2] + tb;
                    pv[4 * r + 0] = re[0]; pv[4 * r + 1] = re[1];
                    pv[4 * r + 2] = re[2]; pv[4 * r + 3] = te;
                }
            }
        }
        __syncthreads();

        // -------- phase 3: H1 (layer 1 + relu), warp = edge-group -----------
        const float4 bb1 = ((float4*)sb1)[lane];
#pragma unroll
        for (int m = 0; m < 4; m++) {
            const int e = warp + 16 * m;
            const int gi = sTgt[2 * e + 1], gj = sTgt[2 * e];
            // node-term gathers (L2-resident tables), issued early
            const float4 Ai = ((const float4*)(g_AB + (size_t)gi * 256))[lane];
            const float4 Bj = ((const float4*)(g_AB + (size_t)gj * 256 + 128))[lane];
            const float4 Aj = ((const float4*)(g_AB + (size_t)gj * 256))[lane];
            const float4 Bi = ((const float4*)(g_AB + (size_t)gi * 256 + 128))[lane];

            float4 et = make_float4(0.f, 0.f, 0.f, 0.f);
            const float* efr = sEF + e * 32;
#pragma unroll 8
            for (int k = 0; k < 32; k++) {
                float4 w = ((float4*)(sW1e + k * 128))[lane];
                fma4(et, efr[k], w);
            }
            float4 qij = make_float4(0.f, 0.f, 0.f, 0.f);
            float4 qji = make_float4(0.f, 0.f, 0.f, 0.f);
            const float* pr = sP + (2 * e) * 12;
#pragma unroll
            for (int k = 0; k < 12; k++) {
                float4 w = ((float4*)(sW1p + k * 128))[lane];
                fma4(qij, pr[k], w);
                fma4(qji, pr[12 + k], w);
            }
            float4 hij, hji;
            hij.x = Ai.x + Bj.x + et.x + qij.x + bb1.x;
            hij.y = Ai.y + Bj.y + et.y + qij.y + bb1.y;
            hij.z = Ai.z + Bj.z + et.z + qij.z + bb1.z;
            hij.w = Ai.w + Bj.w + et.w + qij.w + bb1.w;
            hji.x = Aj.x + Bi.x + et.x + qji.x + bb1.x;
            hji.y = Aj.y + Bi.y + et.y + qji.y + bb1.y;
            hji.z = Aj.z + Bi.z + et.z + qji.z + bb1.z;
            hji.w = Aj.w + Bi.w + et.w + qji.w + bb1.w;
            ((float4*)(sH1 + (2 * e) * 132))[lane]     = relu4(hij);
            ((float4*)(sH1 + (2 * e + 1) * 132))[lane] = relu4(hji);
        }
        __syncthreads();

        // -------- phase 4: layer 2 GEMM (128x128 @ 128x128) + scatter -------
        const float4 bb2 = ((float4*)sb2)[lane];
        float4 acc[8];
#pragma unroll
        for (int r = 0; r < 8; r++) acc[r] = bb2;
        const float* hb = sH1 + (8 * warp) * 132;
#pragma unroll 4
        for (int k = 0; k < 128; k++) {
            float4 w = ((float4*)(sW2 + k * 128))[lane];
#pragma unroll
            for (int r = 0; r < 8; r++) {
                float hv = hb[r * 132 + k];
                fma4(acc[r], hv, w);
            }
        }
#pragma unroll
        for (int r = 0; r < 8; r++) {
            const int row = 8 * warp + r;
            const int tgt = sTgt[row];
            red_add_v4(g_accum + (size_t)tgt * 128 + 4 * lane, relu4(acc[r]));
            if (lane == 0) atomicAdd(&g_cnt[tgt], 1.0f);
        }
    }
}

// ---------------------------------------------------------------------------
// Kernel 3: node MLP (224->128->70) + SE3 epilogue + output assembly
// block = 256 threads, tile = 32 nodes, persistent
// ---------------------------------------------------------------------------
#define NO_W3  0       // 224*128 = 28672
#define NO_W4  28672   // 128*96  = 12288 (cols padded 70->96 with zeros)
#define NO_B3  40960   // 128
#define NO_B4  41088   // 96 (padded)
#define NO_U   41184   // 16*32 = 512
#define NO_G   41696   // 32*228 = 7296
#define NO_H3  48992   // 32*132 = 4224
#define NO_OUT 53216   // 32*72  = 2304
#define NODE_SMEM ((53216 + 2304) * 4)   // 222,080 B

__global__ void __launch_bounds__(256, 1)
k_node(const float* __restrict__ xfeat, const float* __restrict__ T_R,
       const float* __restrict__ T_t, const float* __restrict__ u,
       const int* __restrict__ batch,
       const float* __restrict__ W3, const float* __restrict__ b3,
       const float* __restrict__ W4, const float* __restrict__ b4,
       float* __restrict__ out) {
    extern __shared__ float sm[];
    float* sW3 = sm + NO_W3;
    float* sW4 = sm + NO_W4;
    float* sb3 = sm + NO_B3;
    float* sb4 = sm + NO_B4;
    float* sU  = sm + NO_U;
    float* sG  = sm + NO_G;    // stride 228
    float* sH3 = sm + NO_H3;   // stride 132
    float* sO  = sm + NO_OUT;  // stride 72

    const int tid = threadIdx.x;
    for (int idx = tid; idx < 28672 / 4; idx += 256)
        ((float4*)sW3)[idx] = ((const float4*)W3)[idx];
    for (int idx = tid; idx < 128 * 96; idx += 256) {
        int k = idx / 96, c = idx % 96;
        sW4[idx] = (c < 70) ? W4[k * 70 + c] : 0.f;
    }
    if (tid < 128) sb3[tid] = b3[tid];
    if (tid < 96)  sb4[tid] = (tid < 70) ? b4[tid] : 0.f;
    for (int idx = tid; idx < 512; idx += 256) sU[idx] = u[idx];

    const int warp = tid >> 5, lane = tid & 31;

    for (int tile = blockIdx.x; tile < NN / 32; tile += gridDim.x) {
        const int nb = tile * 32;
        __syncthreads();

        // build G = [aggr(128) | xfeat(64) | u[batch](32)]
        for (int idx = tid; idx < 1024; idx += 256) {
            int n = idx >> 5, c4 = idx & 31;
            int gn = nb + n;
            float4 s = ((const float4*)(g_accum + (size_t)gn * 128))[c4];
            float inv = 1.f / fmaxf(g_cnt[gn], 1.f);
            s.x *= inv; s.y *= inv; s.z *= inv; s.w *= inv;
            ((float4*)(sG + n * 228))[c4] = s;
        }
        for (int idx = tid; idx < 512; idx += 256) {
            int n = idx >> 4, c4 = idx & 15;
            ((float4*)(sG + n * 228 + 128))[c4] =
                ((const float4*)(xfeat + (size_t)(nb + n) * 64))[c4];
        }
        {
            int idx = tid;
            if (idx < 256) {
                int n = idx >> 3, c4 = idx & 7;
                int bn = batch[nb + n];
                ((float4*)(sG + n * 228 + 192))[c4] = ((const float4*)(sU + bn * 32))[c4];
            }
        }
        __syncthreads();

        // GEMM1: H3 = relu(G @ W3 + b3), rows 4w..4w+3, cols 4*lane
        {
            float4 acc[4];
            float4 bb3 = ((float4*)sb3)[lane];
#pragma unroll
            for (int r = 0; r < 4; r++) acc[r] = bb3;
#pragma unroll 4
            for (int k = 0; k < 224; k++) {
                float4 w = ((float4*)(sW3 + k * 128))[lane];
#pragma unroll
                for (int r = 0; r < 4; r++) {
                    float g = sG[(4 * warp + r) * 228 + k];
                    fma4(acc[r], g, w);
                }
            }
#pragma unroll
            for (int r = 0; r < 4; r++)
                ((float4*)(sH3 + (4 * warp + r) * 132))[lane] = relu4(acc[r]);
        }
        __syncthreads();

        // GEMM2: OUT = H3 @ W4 + b4 (70 cols, padded to 96)
        {
            float a0[4], a1[4], a2[4];
            float b40 = sb4[lane], b41 = sb4[32 + lane], b42 = sb4[64 + lane];
#pragma unroll
            for (int r = 0; r < 4; r++) { a0[r] = b40; a1[r] = b41; a2[r] = b42; }
#pragma unroll 4
            for (int k = 0; k < 128; k++) {
                const float* wr = sW4 + k * 96;
                float w0 = wr[lane], w1 = wr[32 + lane], w2 = wr[64 + lane];
#pragma unroll
                for (int r = 0; r < 4; r++) {
                    float h = sH3[(4 * warp + r) * 132 + k];
                    a0[r] = fmaf(h, w0, a0[r]);
                    a1[r] = fmaf(h, w1, a1[r]);
                    a2[r] = fmaf(h, w2, a2[r]);
                }
            }
#pragma unroll
            for (int r = 0; r < 4; r++) {
                float* orow = sO + (4 * warp + r) * 72;
                orow[lane] = a0[r];
                orow[32 + lane] = a1[r];
                if (lane < 6) orow[64 + lane] = a2[r];
            }
        }
        __syncthreads();

        // epilogue: xfeat_out = xfeat + xupd
        for (int idx = tid; idx < 2048; idx += 256) {
            int n = idx >> 6, c = idx & 63;
            int gn = nb + n;
            out[(size_t)gn * 77 + c] = xfeat[(size_t)gn * 64 + c] + sO[n * 72 + c];
        }
        // SE3 exp + compose, one thread per node
        if (tid < 32) {
            const int n = tid, gn = nb + n;
            const float* orow = sO + n * 72;
            float rho0 = orow[64], rho1 = orow[65], rho2 = orow[66];
            float p0 = orow[67], p1 = orow[68], p2 = orow[69];
            float th0 = sqrtf(p0 * p0 + p1 * p1 + p2 * p2);
            float s = PI_F * tanhf(th0 / PI_F) / (th0 + 1e-8f);
            p0 *= s; p1 *= s; p2 *= s;
            float th2 = p0 * p0 + p1 * p1 + p2 * p2;
            float th = sqrtf(th2 + 1e-12f);
            float a, b, c;
            if (th < 1e-4f) {
                a = 1.f - th2 / 6.f;
                b = 0.5f - th2 / 24.f;
                c = 1.f / 6.f - th2 / 120.f;
            } else {
                float sth = sinf(th), cth = cosf(th);
                a = sth / th;
                b = (1.f - cth) / th2;
                c = (th - sth) / (th2 * th);
            }
            // R = I + aK + bK^2, V = I + bK + cK^2 ; K^2 = pp^T - th2*I
            float R[9], V[9];
            R[0] = 1.f + b * (p0 * p0 - th2); R[1] = -a * p2 + b * p0 * p1; R[2] =  a * p1 + b * p0 * p2;
            R[3] =  a * p2 + b * p1 * p0;    R[4] = 1.f + b * (p1 * p1 - th2); R[5] = -a * p0 + b * p1 * p2;
            R[6] = -a * p1 + b * p2 * p0;    R[7] =  a * p0 + b * p2 * p1; R[8] = 1.f + b * (p2 * p2 - th2);
            V[0] = 1.f + c * (p0 * p0 - th2); V[1] = -b * p2 + c * p0 * p1; V[2] =  b * p1 + c * p0 * p2;
            V[3] =  b * p2 + c * p1 * p0;    V[4] = 1.f + c * (p1 * p1 - th2); V[5] = -b * p0 + c * p1 * p2;
            V[6] = -b * p1 + c * p2 * p0;    V[7] =  b * p0 + c * p2 * p1; V[8] = 1.f + c * (p2 * p2 - th2);
            float td0 = V[0] * rho0 + V[1] * rho1 + V[2] * rho2;
            float td1 = V[3] * rho0 + V[4] * rho1 + V[5] * rho2;
            float td2 = V[6] * rho0 + V[7] * rho1 + V[8] * rho2;

            float TRn[9], Ttn[3];
#pragma unroll
            for (int k = 0; k < 9; k++) TRn[k] = T_R[(size_t)gn * 9 + k];
#pragma unroll
            for (int k = 0; k < 3; k++) Ttn[k] = T_t[(size_t)gn * 3 + k];

            float* op = out + (size_t)gn * 77 + 64;
#pragma unroll
            for (int r = 0; r < 3; r++) {
#pragma unroll
                for (int cc = 0; cc < 3; cc++)
                    op[3 * r + cc] = R[r * 3 + 0] * TRn[0 * 3 + cc]
                                   + R[r * 3 + 1] * TRn[1 * 3 + cc]
                                   + R[r * 3 + 2] * TRn[2 * 3 + cc];
            }
            float tdv[3] = {td0, td1, td2};
#pragma unroll
            for (int r = 0; r < 3; r++)
                op[9 + r] = R[r * 3 + 0] * Ttn[0] + R[r * 3 + 1] * Ttn[1]
                          + R[r * 3 + 2] * Ttn[2] + tdv[r];
            op[12] = sqrtf(th2);
        }
    }
}

// ---------------------------------------------------------------------------
// Host launcher
// ---------------------------------------------------------------------------
extern "C" void kernel_launch(void* const* d_in, const int* in_sizes, int n_in,
                              void* d_out, int out_size) {
    (void)in_sizes; (void)n_in; (void)out_size;
    const float* xfeat     = (const float*)d_in[0];
    const float* T_R       = (const float*)d_in[1];
    const float* T_t       = (const float*)d_in[2];
    const float* edge_feat = (const float*)d_in[3];
    const float* Tij_R     = (const float*)d_in[4];
    const float* Tij_t     = (const float*)d_in[5];
    const float* u         = (const float*)d_in[6];
    const int*   edge_idx  = (const int*)d_in[7];
    const int*   batch     = (const int*)d_in[8];
    const float* W1 = (const float*)d_in[9];
    const float* b1 = (const float*)d_in[10];
    const float* W2 = (const float*)d_in[11];
    const float* b2 = (const float*)d_in[12];
    const float* W3 = (const float*)d_in[13];
    const float* b3 = (const float*)d_in[14];
    const float* W4 = (const float*)d_in[15];
    const float* b4 = (const float*)d_in[16];
    float* out = (float*)d_out;

    cudaFuncSetAttribute(k_pre,  cudaFuncAttributeMaxDynamicSharedMemorySize, PRE_SMEM);
    cudaFuncSetAttribute(k_edge, cudaFuncAttributeMaxDynamicSharedMemorySize, EDGE_SMEM);
    cudaFuncSetAttribute(k_node, cudaFuncAttributeMaxDynamicSharedMemorySize, NODE_SMEM);

    k_pre<<<148, 256, PRE_SMEM>>>(xfeat, W1);
    k_edge<<<148, 512, EDGE_SMEM>>>(T_R, T_t, edge_feat, Tij_R, Tij_t,
                                    edge_idx, W1, b1, W2, b2);
    k_node<<<148, 256, NODE_SMEM>>>(xfeat, T_R, T_t, u, batch,
                                    W3, b3, W4, b4, out);
}

// round 10
// speedup vs baseline: 1.0032x; 1.0032x over previous
#include <cuda_runtime.h>
#include <math.h>

// Problem constants
#define NN 20000
#define EE 200000
#define BBATCH 16
#define ND 64
#define ED 32
#define GD 32
#define HD 128
#define DOF 6
#define PI_F 3.14159265358979f

typedef unsigned long long ull;

// ---------------------------------------------------------------------------
// Scratch (static __device__ arrays; no allocation allowed)
// ---------------------------------------------------------------------------
__device__ float g_AB[(size_t)NN * 256];     // per-node A (x@W1a) [0:128], B (x@W1b) [128:256]
__device__ float g_accum[(size_t)NN * HD];   // segment sums
__device__ float g_cnt[NN];                  // segment counts

// ---- packed f32x2 helpers (FFMA2: 2 MACs per fma-pipe inst; ptxas never
// emits these from C++, only via PTX) ----
#define PACK2(d, s)      asm("mov.b64 %0, {%1, %1};" : "=l"(d) : "f"(s))
#define UNPK2(lo, hi, v) asm("mov.b64 {%0, %1}, %2;" : "=f"(lo), "=f"(hi) : "l"(v))
#define FMA2(acc, a, b)  asm("fma.rn.f32x2 %0, %1, %2, %0;" : "+l"(acc) : "l"(a), "l"(b))
#define ADD2(d, a, b)    asm("add.rn.f32x2 %0, %1, %2;" : "=l"(d) : "l"(a), "l"(b))

__device__ __forceinline__ float4 relu4(float4 v) {
    v.x = fmaxf(v.x, 0.f); v.y = fmaxf(v.y, 0.f);
    v.z = fmaxf(v.z, 0.f); v.w = fmaxf(v.w, 0.f);
    return v;
}

__device__ __forceinline__ void red_add_v4(float* p, float4 v) {
    asm volatile("red.global.add.v4.f32 [%0], {%1,%2,%3,%4};"
                 :: "l"(p), "f"(v.x), "f"(v.y), "f"(v.z), "f"(v.w) : "memory");
}

// ---------------------------------------------------------------------------
// Kernel 1: per-node precompute A = x@W1[0:64], B = x@W1[64:128]; zero accum/cnt
// block = 512 threads (16 warps), tile = 64 nodes, persistent grid-stride
// smem: W1ab 128x128 (65536B) + X 64x68 (17408B) = 82944B
// ---------------------------------------------------------------------------
#define PRE_SMEM ((128 * 128 + 64 * 68) * 4)

__global__ void __launch_bounds__(512, 1)
k_pre(const float* __restrict__ xfeat, const float* __restrict__ W1) {
    extern __shared__ float sm[];
    float* sW = sm;              // 128*128
    float* sX = sm + 128 * 128;  // 64*68 (padded)

    for (int idx = threadIdx.x; idx < (128 * 128) / 4; idx += 512)
        ((float4*)sW)[idx] = ((const float4*)W1)[idx];

    const int warp = threadIdx.x >> 5, lane = threadIdx.x & 31;
    const int NT = (NN + 63) / 64;   // 313 (last tile partial)

    for (int tile = blockIdx.x; tile < NT; tile += gridDim.x) {
        const int nb = tile * 64;
        const int nrem = min(64, NN - nb);
        __syncthreads();
        for (int idx = threadIdx.x; idx < nrem * 16; idx += 512) {
            int n = idx >> 4, k4 = idx & 15;
            ((float4*)(sX + n * 68))[k4] =
                ((const float4*)(xfeat + (size_t)(nb + n) * 64))[k4];
        }
        __syncthreads();

        ull accA[4][2], accB[4][2];
#pragma unroll
        for (int r = 0; r < 4; r++) {
            accA[r][0] = 0ull; accA[r][1] = 0ull;
            accB[r][0] = 0ull; accB[r][1] = 0ull;
        }
#pragma unroll 4
        for (int k = 0; k < 64; k++) {
            ulonglong2 wa = *(const ulonglong2*)(sW + k * 128 + 4 * lane);
            ulonglong2 wb = *(const ulonglong2*)(sW + (64 + k) * 128 + 4 * lane);
#pragma unroll
            for (int r = 0; r < 4; r++) {
                float x = sX[(4 * warp + r) * 68 + k];
                ull xx; PACK2(xx, x);
                FMA2(accA[r][0], xx, wa.x); FMA2(accA[r][1], xx, wa.y);
                FMA2(accB[r][0], xx, wb.x); FMA2(accB[r][1], xx, wb.y);
            }
        }
#pragma unroll
        for (int r = 0; r < 4; r++) {
            int gn = nb + 4 * warp + r;
            if (gn < NN) {
                float4 oa, ob;
                UNPK2(oa.x, oa.y, accA[r][0]); UNPK2(oa.z, oa.w, accA[r][1]);
                UNPK2(ob.x, ob.y, accB[r][0]); UNPK2(ob.z, ob.w, accB[r][1]);
                ((float4*)(g_AB + (size_t)gn * 256))[lane] = oa;
                ((float4*)(g_AB + (size_t)gn * 256 + 128))[lane] = ob;
                ((float4*)(g_accum + (size_t)gn * 128))[lane] = make_float4(0.f, 0.f, 0.f, 0.f);
                if (lane == 0) g_cnt[gn] = 0.f;
            }
        }
    }
}

// ---------------------------------------------------------------------------
// Kernel 2: fused edge MLP (layer1 factorized + layer2 GEMM) + atomic scatter
// block = 512 threads (16 warps), tile = 64 edges -> 128 direction-rows
// ---------------------------------------------------------------------------
// smem float offsets
#define EO_W2  0       // 128*128 = 16384
#define EO_W1E 16384   // 32*128  = 4096
#define EO_W1P 20480   // 12*128  = 1536
#define EO_B1  22016   // 128
#define EO_B2  22144   // 128
#define EO_EF  22272   // 64*32   = 2048
#define EO_P   24320   // 128*12  = 1536
#define EO_H1  25856   // 128*132 = 16896
#define EO_TGT 42752   // 128 ints
#define EDGE_SMEM ((42752 + 128) * 4)   // 171,520 B

__global__ void __launch_bounds__(512, 1)
k_edge(const float* __restrict__ T_R, const float* __restrict__ T_t,
       const float* __restrict__ edge_feat,
       const float* __restrict__ Tij_R, const float* __restrict__ Tij_t,
       const int* __restrict__ edge_index,
       const float* __restrict__ W1, const float* __restrict__ b1,
       const float* __restrict__ W2, const float* __restrict__ b2) {
    extern __shared__ float sm[];
    float* sW2  = sm + EO_W2;
    float* sW1e = sm + EO_W1E;
    float* sW1p = sm + EO_W1P;
    float* sb1  = sm + EO_B1;
    float* sb2  = sm + EO_B2;
    float* sEF  = sm + EO_EF;
    float* sP   = sm + EO_P;
    float* sH1  = sm + EO_H1;
    int*   sTgt = (int*)(sm + EO_TGT);

    const int tid = threadIdx.x;
    for (int idx = tid; idx < 16384 / 4; idx += 512)
        ((float4*)sW2)[idx] = ((const float4*)W2)[idx];
    for (int idx = tid; idx < 4096 / 4; idx += 512)
        ((float4*)sW1e)[idx] = ((const float4*)(W1 + 128 * 128))[idx];
    for (int idx = tid; idx < 1536 / 4; idx += 512)
        ((float4*)sW1p)[idx] = ((const float4*)(W1 + 160 * 128))[idx];
    if (tid < 128) { sb1[tid] = b1[tid]; sb2[tid] = b2[tid]; }
    __syncthreads();

    const int warp = tid >> 5, lane = tid & 31;
    // hoisted packed biases (per-lane constant across tiles)
    const ulonglong2 b1p = *(const ulonglong2*)(sb1 + 4 * lane);
    const ulonglong2 b2p = *(const ulonglong2*)(sb2 + 4 * lane);

    for (int tile = blockIdx.x; tile < EE / 64; tile += gridDim.x) {
        const int eb = tile * 64;
        __syncthreads();   // previous tile fully consumed

        // edge_feat tile (contiguous, coalesced): exactly 512 float4s
        ((float4*)sEF)[tid] = ((const float4*)(edge_feat + (size_t)eb * 32))[tid];

        // pose vectors: one thread per edge
        if (tid < 64) {
            const int e = tid, ge = eb + e;
            const int gi = edge_index[ge];
            const int gj = edge_index[EE + ge];
            sTgt[2 * e]     = gj;   // f_ij aggregates into j
            sTgt[2 * e + 1] = gi;   // f_ji aggregates into i

            float Ri[9], Rj[9], TRm[9], ti[3], tj[3], Tt[3];
#pragma unroll
            for (int k = 0; k < 9; k++) {
                Ri[k]  = T_R[(size_t)gi * 9 + k];
                Rj[k]  = T_R[(size_t)gj * 9 + k];
                TRm[k] = Tij_R[(size_t)ge * 9 + k];
            }
#pragma unroll
            for (int k = 0; k < 3; k++) {
                ti[k] = T_t[(size_t)gi * 3 + k];
                tj[k] = T_t[(size_t)gj * 3 + k];
                Tt[k] = Tij_t[(size_t)ge * 3 + k];
            }
            // Ra = Rj * Ri^T ; ta = tj - Ra*ti
            float Ra[9], ta[3];
#pragma unroll
            for (int r = 0; r < 3; r++) {
#pragma unroll
                for (int c = 0; c < 3; c++)
                    Ra[r * 3 + c] = Rj[r * 3 + 0] * Ri[c * 3 + 0]
                                  + Rj[r * 3 + 1] * Ri[c * 3 + 1]
                                  + Rj[r * 3 + 2] * Ri[c * 3 + 2];
                ta[r] = tj[r] - (Ra[r * 3 + 0] * ti[0] + Ra[r * 3 + 1] * ti[1]
                               + Ra[r * 3 + 2] * ti[2]);
            }
            // e_ij = (Ra, ta) * inv(Tij): R = Ra*TR^T, t = ta - R*Tt
            {
                float* pv = sP + (2 * e) * 12;
#pragma unroll
                for (int r = 0; r < 3; r++) {
                    float re[3];
#pragma unroll
                    for (int c = 0; c < 3; c++)
                        re[c] = Ra[r * 3 + 0] * TRm[c * 3 + 0]
                              + Ra[r * 3 + 1] * TRm[c * 3 + 1]
                              + Ra[r * 3 + 2] * TRm[c * 3 + 2];
                    float te = ta[r] - (re[0] * Tt[0] + re[1] * Tt[1] + re[2] * Tt[2]);
                    pv[4 * r + 0] = re[0]; pv[4 * r + 1] = re[1];
                    pv[4 * r + 2] = re[2]; pv[4 * r + 3] = te;
                }
            }
            // e_ji: Rb = Ra^T, tb = ti - Rb*tj; R = Rb*TR, t = Rb*Tt + tb
            {
                float* pv = sP + (2 * e + 1) * 12;
#pragma unroll
                for (int r = 0; r < 3; r++) {
                    float bv0 = Ra[0 * 3 + r], bv1 = Ra[1 * 3 + r], bv2 = Ra[2 * 3 + r];
                    float tb = ti[r] - (bv0 * tj[0] + bv1 * tj[1] + bv2 * tj[2]);
                    float re[3];
#pragma unroll
                    for (int c = 0; c < 3; c++)
                        re[c] = bv0 * TRm[0 * 3 + c] + bv1 * TRm[1 * 3 + c] + bv2 * TRm[2 * 3 + c];
                    float te = bv0 * Tt[0] + bv1 * Tt[1] + bv2 * Tt[2] + tb;
                    pv[4 * r + 0] = re[0]; pv[4 * r + 1] = re[1];
                    pv[4 * r + 2] = re[2]; pv[4 * r + 3] = te;
                }
            }
        }
        __syncthreads();

        // -------- phase 3: H1 (layer 1 + relu), warp = edge-group -----------
#pragma unroll
        for (int m = 0; m < 4; m++) {
            const int e = warp + 16 * m;
            const int gi = sTgt[2 * e + 1], gj = sTgt[2 * e];
            // node-term gathers (L2-resident tables), issued early
            const ulonglong2 Ai = ((const ulonglong2*)(g_AB + (size_t)gi * 256))[lane];
            const ulonglong2 Bj = ((const ulonglong2*)(g_AB + (size_t)gj * 256 + 128))[lane];
            const ulonglong2 Aj = ((const ulonglong2*)(g_AB + (size_t)gj * 256))[lane];
            const ulonglong2 Bi = ((const ulonglong2*)(g_AB + (size_t)gi * 256 + 128))[lane];

            ull et0 = 0ull, et1 = 0ull;
            const float* efr = sEF + e * 32;
#pragma unroll 8
            for (int k = 0; k < 32; k++) {
                ulonglong2 w = *(const ulonglong2*)(sW1e + k * 128 + 4 * lane);
                ull e2; PACK2(e2, efr[k]);
                FMA2(et0, e2, w.x); FMA2(et1, e2, w.y);
            }
            ull q0 = 0ull, q1 = 0ull, p0 = 0ull, p1 = 0ull;
            const float* pr = sP + (2 * e) * 12;
#pragma unroll
            for (int k = 0; k < 12; k++) {
                ulonglong2 w = *(const ulonglong2*)(sW1p + k * 128 + 4 * lane);
                ull a2; PACK2(a2, pr[k]);
                ull c2; PACK2(c2, pr[12 + k]);
                FMA2(q0, a2, w.x); FMA2(q1, a2, w.y);
                FMA2(p0, c2, w.x); FMA2(p1, c2, w.y);
            }
            // hij = Ai + Bj + et + q + b1 ; hji = Aj + Bi + et + p + b1 (packed)
            ull s0, s1, t0, t1;
            ADD2(s0, Ai.x, Bj.x); ADD2(s0, s0, et0); ADD2(s0, s0, q0); ADD2(s0, s0, b1p.x);
            ADD2(s1, Ai.y, Bj.y); ADD2(s1, s1, et1); ADD2(s1, s1, q1); ADD2(s1, s1, b1p.y);
            ADD2(t0, Aj.x, Bi.x); ADD2(t0, t0, et0); ADD2(t0, t0, p0); ADD2(t0, t0, b1p.x);
            ADD2(t1, Aj.y, Bi.y); ADD2(t1, t1, et1); ADD2(t1, t1, p1); ADD2(t1, t1, b1p.y);
            float4 hij, hji;
            UNPK2(hij.x, hij.y, s0); UNPK2(hij.z, hij.w, s1);
            UNPK2(hji.x, hji.y, t0); UNPK2(hji.z, hji.w, t1);
            ((float4*)(sH1 + (2 * e) * 132))[lane]     = relu4(hij);
            ((float4*)(sH1 + (2 * e + 1) * 132))[lane] = relu4(hji);
        }
        __syncthreads();

        // -------- phase 4: layer 2 GEMM (128x128 @ 128x128) + scatter -------
        ull acc[8][2];
#pragma unroll
        for (int r = 0; r < 8; r++) { acc[r][0] = b2p.x; acc[r][1] = b2p.y; }
        const float* hb = sH1 + (8 * warp) * 132;
#pragma unroll 2
        for (int k = 0; k < 128; k += 4) {
            ulonglong2 w0 = *(const ulonglong2*)(sW2 + (k + 0) * 128 + 4 * lane);
            ulonglong2 w1 = *(const ulonglong2*)(sW2 + (k + 1) * 128 + 4 * lane);
            ulonglong2 w2 = *(const ulonglong2*)(sW2 + (k + 2) * 128 + 4 * lane);
            ulonglong2 w3 = *(const ulonglong2*)(sW2 + (k + 3) * 128 + 4 * lane);
#pragma unroll
            for (int r = 0; r < 8; r++) {
                float4 h4 = *(const float4*)(hb + r * 132 + k);  // warp-broadcast
                ull h0; PACK2(h0, h4.x);
                FMA2(acc[r][0], h0, w0.x); FMA2(acc[r][1], h0, w0.y);
                ull h1; PACK2(h1, h4.y);
                FMA2(acc[r][0], h1, w1.x); FMA2(acc[r][1], h1, w1.y);
                ull h2; PACK2(h2, h4.z);
                FMA2(acc[r][0], h2, w2.x); FMA2(acc[r][1], h2, w2.y);
                ull h3; PACK2(h3, h4.w);
                FMA2(acc[r][0], h3, w3.x); FMA2(acc[r][1], h3, w3.y);
            }
        }
#pragma unroll
        for (int r = 0; r < 8; r++) {
            const int row = 8 * warp + r;
            const int tgt = sTgt[row];
            float4 o;
            UNPK2(o.x, o.y, acc[r][0]); UNPK2(o.z, o.w, acc[r][1]);
            red_add_v4(g_accum + (size_t)tgt * 128 + 4 * lane, relu4(o));
            if (lane == 0) atomicAdd(&g_cnt[tgt], 1.0f);
        }
    }
}

// ---------------------------------------------------------------------------
// Kernel 3: node MLP (224->128->70) + SE3 epilogue + output assembly
// block = 256 threads, tile = 32 nodes, persistent
// ---------------------------------------------------------------------------
#define NO_W3  0       // 224*128 = 28672
#define NO_W4  28672   // 128*96  = 12288 (cols padded 70->96 with zeros)
#define NO_B3  40960   // 128
#define NO_B4  41088   // 96 (padded)
#define NO_U   41184   // 16*32 = 512
#define NO_G   41696   // 32*228 = 7296
#define NO_H3  48992   // 32*132 = 4224
#define NO_OUT 53216   // 32*72  = 2304
#define NODE_SMEM ((53216 + 2304) * 4)   // 222,080 B

__global__ void __launch_bounds__(256, 1)
k_node(const float* __restrict__ xfeat, const float* __restrict__ T_R,
       const float* __restrict__ T_t, const float* __restrict__ u,
       const int* __restrict__ batch,
       const float* __restrict__ W3, const float* __restrict__ b3,
       const float* __restrict__ W4, const float* __restrict__ b4,
       float* __restrict__ out) {
    extern __shared__ float sm[];
    float* sW3 = sm + NO_W3;
    float* sW4 = sm + NO_W4;
    float* sb3 = sm + NO_B3;
    float* sb4 = sm + NO_B4;
    float* sU  = sm + NO_U;
    float* sG  = sm + NO_G;    // stride 228
    float* sH3 = sm + NO_H3;   // stride 132
    float* sO  = sm + NO_OUT;  // stride 72

    const int tid = threadIdx.x;
    for (int idx = tid; idx < 28672 / 4; idx += 256)
        ((float4*)sW3)[idx] = ((const float4*)W3)[idx];
    for (int idx = tid; idx < 128 * 96; idx += 256) {
        int k = idx / 96, c = idx % 96;
        sW4[idx] = (c < 70) ? W4[k * 70 + c] : 0.f;
    }
    if (tid < 128) sb3[tid] = b3[tid];
    if (tid < 96)  sb4[tid] = (tid < 70) ? b4[tid] : 0.f;
    for (int idx = tid; idx < 512; idx += 256) sU[idx] = u[idx];
    __syncthreads();

    const int warp = tid >> 5, lane = tid & 31;
    const ulonglong2 b3p = *(const ulonglong2*)(sb3 + 4 * lane);

    for (int tile = blockIdx.x; tile < NN / 32; tile += gridDim.x) {
        const int nb = tile * 32;
        __syncthreads();

        // build G = [aggr(128) | xfeat(64) | u[batch](32)]
        for (int idx = tid; idx < 1024; idx += 256) {
            int n = idx >> 5, c4 = idx & 31;
            int gn = nb + n;
            float4 s = ((const float4*)(g_accum + (size_t)gn * 128))[c4];
            float inv = 1.f / fmaxf(g_cnt[gn], 1.f);
            s.x *= inv; s.y *= inv; s.z *= inv; s.w *= inv;
            ((float4*)(sG + n * 228))[c4] = s;
        }
        for (int idx = tid; idx < 512; idx += 256) {
            int n = idx >> 4, c4 = idx & 15;
            ((float4*)(sG + n * 228 + 128))[c4] =
                ((const float4*)(xfeat + (size_t)(nb + n) * 64))[c4];
        }
        if (tid < 256) {
            int n = tid >> 3, c4 = tid & 7;
            int bn = batch[nb + n];
            ((float4*)(sG + n * 228 + 192))[c4] = ((const float4*)(sU + bn * 32))[c4];
        }
        __syncthreads();

        // GEMM1: H3 = relu(G @ W3 + b3), rows 4w..4w+3, cols 4*lane (packed)
        {
            ull acc[4][2];
#pragma unroll
            for (int r = 0; r < 4; r++) { acc[r][0] = b3p.x; acc[r][1] = b3p.y; }
#pragma unroll 4
            for (int k = 0; k < 224; k++) {
                ulonglong2 w = *(const ulonglong2*)(sW3 + k * 128 + 4 * lane);
#pragma unroll
                for (int r = 0; r < 4; r++) {
                    ull g2; PACK2(g2, sG[(4 * warp + r) * 228 + k]);
                    FMA2(acc[r][0], g2, w.x); FMA2(acc[r][1], g2, w.y);
                }
            }
#pragma unroll
            for (int r = 0; r < 4; r++) {
                float4 o;
                UNPK2(o.x, o.y, acc[r][0]); UNPK2(o.z, o.w, acc[r][1]);
                ((float4*)(sH3 + (4 * warp + r) * 132))[lane] = relu4(o);
            }
        }
        __syncthreads();

        // GEMM2: OUT = H3 @ W4 + b4 (70 cols, padded to 96)
        {
            float a0[4], a1[4], a2[4];
            float b40 = sb4[lane], b41 = sb4[32 + lane], b42 = sb4[64 + lane];
#pragma unroll
            for (int r = 0; r < 4; r++) { a0[r] = b40; a1[r] = b41; a2[r] = b42; }
#pragma unroll 4
            for (int k = 0; k < 128; k++) {
                const float* wr = sW4 + k * 96;
                float w0 = wr[lane], w1 = wr[32 + lane], w2 = wr[64 + lane];
#pragma unroll
                for (int r = 0; r < 4; r++) {
                    float h = sH3[(4 * warp + r) * 132 + k];
                    a0[r] = fmaf(h, w0, a0[r]);
                    a1[r] = fmaf(h, w1, a1[r]);
                    a2[r] = fmaf(h, w2, a2[r]);
                }
            }
#pragma unroll
            for (int r = 0; r < 4; r++) {
                float* orow = sO + (4 * warp + r) * 72;
                orow[lane] = a0[r];
                orow[32 + lane] = a1[r];
                if (lane < 6) orow[64 + lane] = a2[r];
            }
        }
        __syncthreads();

        // epilogue: xfeat_out = xfeat + xupd
        for (int idx = tid; idx < 2048; idx += 256) {
            int n = idx >> 6, c = idx & 63;
            int gn = nb + n;
            out[(size_t)gn * 77 + c] = xfeat[(size_t)gn * 64 + c] + sO[n * 72 + c];
        }
        // SE3 exp + compose, one thread per node
        if (tid < 32) {
            const int n = tid, gn = nb + n;
            const float* orow = sO + n * 72;
            float rho0 = orow[64], rho1 = orow[65], rho2 = orow[66];
            float p0 = orow[67], p1 = orow[68], p2 = orow[69];
            float th0 = sqrtf(p0 * p0 + p1 * p1 + p2 * p2);
            float s = PI_F * tanhf(th0 / PI_F) / (th0 + 1e-8f);
            p0 *= s; p1 *= s; p2 *= s;
            float th2 = p0 * p0 + p1 * p1 + p2 * p2;
            float th = sqrtf(th2 + 1e-12f);
            float a, b, c;
            if (th < 1e-4f) {
                a = 1.f - th2 / 6.f;
                b = 0.5f - th2 / 24.f;
                c = 1.f / 6.f - th2 / 120.f;
            } else {
                float sth = sinf(th), cth = cosf(th);
                a = sth / th;
                b = (1.f - cth) / th2;
                c = (th - sth) / (th2 * th);
            }
            // R = I + aK + bK^2, V = I + bK + cK^2 ; K^2 = pp^T - th2*I
            float R[9], V[9];
            R[0] = 1.f + b * (p0 * p0 - th2); R[1] = -a * p2 + b * p0 * p1; R[2] =  a * p1 + b * p0 * p2;
            R[3] =  a * p2 + b * p1 * p0;    R[4] = 1.f + b * (p1 * p1 - th2); R[5] = -a * p0 + b * p1 * p2;
            R[6] = -a * p1 + b * p2 * p0;    R[7] =  a * p0 + b * p2 * p1; R[8] = 1.f + b * (p2 * p2 - th2);
            V[0] = 1.f + c * (p0 * p0 - th2); V[1] = -b * p2 + c * p0 * p1; V[2] =  b * p1 + c * p0 * p2;
            V[3] =  b * p2 + c * p1 * p0;    V[4] = 1.f + c * (p1 * p1 - th2); V[5] = -b * p0 + c * p1 * p2;
            V[6] = -b * p1 + c * p2 * p0;    V[7] =  b * p0 + c * p2 * p1; V[8] = 1.f + c * (p2 * p2 - th2);
            float td0 = V[0] * rho0 + V[1] * rho1 + V[2] * rho2;
            float td1 = V[3] * rho0 + V[4] * rho1 + V[5] * rho2;
            float td2 = V[6] * rho0 + V[7] * rho1 + V[8] * rho2;

            float TRn[9], Ttn[3];
#pragma unroll
            for (int k = 0; k < 9; k++) TRn[k] = T_R[(size_t)gn * 9 + k];
#pragma unroll
            for (int k = 0; k < 3; k++) Ttn[k] = T_t[(size_t)gn * 3 + k];

            float* op = out + (size_t)gn * 77 + 64;
#pragma unroll
            for (int r = 0; r < 3; r++) {
#pragma unroll
                for (int cc = 0; cc < 3; cc++)
                    op[3 * r + cc] = R[r * 3 + 0] * TRn[0 * 3 + cc]
                                   + R[r * 3 + 1] * TRn[1 * 3 + cc]
                                   + R[r * 3 + 2] * TRn[2 * 3 + cc];
            }
            float tdv[3] = {td0, td1, td2};
#pragma unroll
            for (int r = 0; r < 3; r++)
                op[9 + r] = R[r * 3 + 0] * Ttn[0] + R[r * 3 + 1] * Ttn[1]
                          + R[r * 3 + 2] * Ttn[2] + tdv[r];
            op[12] = sqrtf(th2);
        }
    }
}

// ---------------------------------------------------------------------------
// Host launcher
// ---------------------------------------------------------------------------
extern "C" void kernel_launch(void* const* d_in, const int* in_sizes, int n_in,
                              void* d_out, int out_size) {
    (void)in_sizes; (void)n_in; (void)out_size;
    const float* xfeat     = (const float*)d_in[0];
    const float* T_R       = (const float*)d_in[1];
    const float* T_t       = (const float*)d_in[2];
    const float* edge_feat = (const float*)d_in[3];
    const float* Tij_R     = (const float*)d_in[4];
    const float* Tij_t     = (const float*)d_in[5];
    const float* u         = (const float*)d_in[6];
    const int*   edge_idx  = (const int*)d_in[7];
    const int*   batch     = (const int*)d_in[8];
    const float* W1 = (const float*)d_in[9];
    const float* b1 = (const float*)d_in[10];
    const float* W2 = (const float*)d_in[11];
    const float* b2 = (const float*)d_in[12];
    const float* W3 = (const float*)d_in[13];
    const float* b3 = (const float*)d_in[14];
    const float* W4 = (const float*)d_in[15];
    const float* b4 = (const float*)d_in[16];
    float* out = (float*)d_out;

    cudaFuncSetAttribute(k_pre,  cudaFuncAttributeMaxDynamicSharedMemorySize, PRE_SMEM);
    cudaFuncSetAttribute(k_edge, cudaFuncAttributeMaxDynamicSharedMemorySize, EDGE_SMEM);
    cudaFuncSetAttribute(k_node, cudaFuncAttributeMaxDynamicSharedMemorySize, NODE_SMEM);

    k_pre<<<148, 512, PRE_SMEM>>>(xfeat, W1);
    k_edge<<<148, 512, EDGE_SMEM>>>(T_R, T_t, edge_feat, Tij_R, Tij_t,
                                    edge_idx, W1, b1, W2, b2);
    k_node<<<148, 256, NODE_SMEM>>>(xfeat, T_R, T_t, u, batch,
                                    W3, b3, W4, b4, out);
}